// round 6
// baseline (speedup 1.0000x reference)
#include <cuda_runtime.h>
#include <cstdint>

// Output layout:
//   [0,       N*D)      mean_messages (float)
//   [N*D,     N*D+N)    last_timestamps (float)
//   [N*D+N,   N*D+2N)   counts (float)

#define MAX_B        (1 << 21)
#define MAX_N        (1 << 18)
#define PREP_BLOCKS  592          // 148 * 4, all resident (256 thr, launch_bounds)
#define PREP_THREADS 256
#define SCAN_CHUNK   1024         // elements per scan block (256 thr x 4)
#define MAX_NBS      (MAX_N / SCAN_CHUNK)

// One memset zeroes barrier counter + histogram (contiguous region).
__device__ __align__(16) unsigned g_zero_region[64 + MAX_N];
#define G_BARRIER (g_zero_region[0])
#define G_HIST    ((int*)(g_zero_region + 64))

__device__ int g_off[MAX_N];
__device__ int g_cur[MAX_N];
__device__ int g_order[MAX_B];
__device__ int g_bsum[MAX_NBS + 1];

// ---------------- software grid barrier (all blocks resident) --------------
__device__ __forceinline__ void grid_barrier(unsigned gen, unsigned nb) {
    __syncthreads();
    if (threadIdx.x == 0) {
        __threadfence();
        atomicAdd(&G_BARRIER, 1u);
        unsigned target = gen * nb;
        while (atomicAdd(&G_BARRIER, 0u) < target) __nanosleep(64);
        __threadfence();
    }
    __syncthreads();
}

// ---------------- block exclusive scan (works for any nwarps <= 32) --------
__device__ __forceinline__ int block_excl_scan(int v, int tid, int nwarps,
                                               int* total) {
    int lane = tid & 31, wid = tid >> 5;
    __shared__ int wsum[32];
    __syncthreads();                 // safe reuse across repeated calls
    int inc = v;
    #pragma unroll
    for (int d = 1; d < 32; d <<= 1) {
        int t = __shfl_up_sync(0xffffffffu, inc, d);
        if (lane >= d) inc += t;
    }
    if (lane == 31) wsum[wid] = inc;
    __syncthreads();
    if (wid == 0) {
        int w = (lane < nwarps) ? wsum[lane] : 0;   // FIX: don't read garbage
        #pragma unroll
        for (int d = 1; d < 32; d <<= 1) {
            int t = __shfl_up_sync(0xffffffffu, w, d);
            if (lane >= d) w += t;
        }
        wsum[lane] = w;
    }
    __syncthreads();
    int excl = inc - v + (wid > 0 ? wsum[wid - 1] : 0);
    if (total) *total = wsum[nwarps - 1];
    return excl;
}

// ---------------- fused prep: hist -> scan -> bin, one launch --------------
__global__ void __launch_bounds__(PREP_THREADS, 4)
prep_kernel(const int4* __restrict__ ids4, int B4,
            const int* __restrict__ ids, int B, int N, int NBS) {
    const int tid = threadIdx.x;
    const int bid = blockIdx.x;
    const unsigned nb = gridDim.x;
    const int stride = nb * PREP_THREADS;
    const int nwarps = PREP_THREADS >> 5;   // 8

    // ---- phase 1: histogram (grid-stride) ----
    for (int i = bid * PREP_THREADS + tid; i < B4; i += stride) {
        int4 v = ids4[i];
        atomicAdd(&G_HIST[v.x], 1);
        atomicAdd(&G_HIST[v.y], 1);
        atomicAdd(&G_HIST[v.z], 1);
        atomicAdd(&G_HIST[v.w], 1);
    }
    if (bid == 0 && tid < (B - B4 * 4))
        atomicAdd(&G_HIST[ids[B4 * 4 + tid]], 1);
    grid_barrier(1, nb);

    // ---- phase 2a: per-block local scan over SCAN_CHUNK elements ----
    if (bid < NBS) {
        int base = bid * SCAN_CHUNK;
        int i0 = base + tid * 4;
        int4 h = make_int4(0, 0, 0, 0);
        if (i0 + 3 < N) {
            h = *(const int4*)&G_HIST[i0];
        } else {
            if (i0     < N) h.x = G_HIST[i0];
            if (i0 + 1 < N) h.y = G_HIST[i0 + 1];
            if (i0 + 2 < N) h.z = G_HIST[i0 + 2];
            if (i0 + 3 < N) h.w = G_HIST[i0 + 3];
        }
        int s = h.x + h.y + h.z + h.w;
        int tot;
        int excl = block_excl_scan(s, tid, nwarps, &tot);
        if (i0     < N) g_off[i0]     = excl;
        if (i0 + 1 < N) g_off[i0 + 1] = excl + h.x;
        if (i0 + 2 < N) g_off[i0 + 2] = excl + h.x + h.y;
        if (i0 + 3 < N) g_off[i0 + 3] = excl + h.x + h.y + h.z;
        if (tid == 0) g_bsum[bid] = tot;
    }
    grid_barrier(2, nb);

    // ---- phase 2b: block 0 scans the block totals ----
    if (bid == 0) {
        int v = (tid < NBS) ? g_bsum[tid] : 0;
        int excl = block_excl_scan(v, tid, nwarps, nullptr);
        if (tid < NBS) g_bsum[tid] = excl;
    }
    grid_barrier(3, nb);

    // ---- phase 2c: add block offsets, init cursors ----
    if (bid < NBS) {
        int add = g_bsum[bid];
        int base = bid * SCAN_CHUNK;
        #pragma unroll
        for (int j = 0; j < 4; j++) {
            int i = base + j * PREP_THREADS + tid;
            if (i < N) {
                int o = g_off[i] + add;
                g_off[i] = o;
                g_cur[i] = o;
            }
        }
    }
    grid_barrier(4, nb);

    // ---- phase 3: bin event indices (grid-stride) ----
    for (int i = bid * PREP_THREADS + tid; i < B4; i += stride) {
        int4 v = ids4[i];
        int e = i * 4;
        g_order[atomicAdd(&g_cur[v.x], 1)] = e;
        g_order[atomicAdd(&g_cur[v.y], 1)] = e + 1;
        g_order[atomicAdd(&g_cur[v.z], 1)] = e + 2;
        g_order[atomicAdd(&g_cur[v.w], 1)] = e + 3;
    }
    if (bid == 0 && tid < (B - B4 * 4)) {
        int e = B4 * 4 + tid;
        g_order[atomicAdd(&g_cur[ids[e]], 1)] = e;
    }
}

// ---------------- gather-sum: TWO warps per node, 4-event unroll -----------
__global__ void __launch_bounds__(256, 8)
sum_kernel(const float4* __restrict__ messages4, // [B, Dq]
           const float* __restrict__ ts,         // [B]
           float4* __restrict__ sums4,           // [N, Dq]
           float* __restrict__ last_ts,          // [N]
           float* __restrict__ counts,           // [N]
           int N, int Dq /* = D/4 = 64 */) {
    int gw   = blockIdx.x * (blockDim.x >> 5) + (threadIdx.x >> 5);
    int lane = threadIdx.x & 31;
    int node = gw >> 1;
    int half = gw & 1;
    if (node >= N) return;

    int c = G_HIST[node];
    int start = g_off[node];
    int col = half * 32 + lane;

    float4 acc = make_float4(0.f, 0.f, 0.f, 0.f);
    int emax = -1;

    for (int base = 0; base < c; base += 32) {
        int m = min(32, c - base);
        int idx = (lane < m) ? __ldg(&g_order[start + base + lane]) : -1;
        emax = max(emax, idx);

        int k = 0;
        for (; k + 4 <= m; k += 4) {
            int e0 = __shfl_sync(0xffffffffu, idx, k);
            int e1 = __shfl_sync(0xffffffffu, idx, k + 1);
            int e2 = __shfl_sync(0xffffffffu, idx, k + 2);
            int e3 = __shfl_sync(0xffffffffu, idx, k + 3);
            float4 r0 = __ldg(&messages4[(long long)e0 * Dq + col]);
            float4 r1 = __ldg(&messages4[(long long)e1 * Dq + col]);
            float4 r2 = __ldg(&messages4[(long long)e2 * Dq + col]);
            float4 r3 = __ldg(&messages4[(long long)e3 * Dq + col]);
            acc.x += r0.x; acc.y += r0.y; acc.z += r0.z; acc.w += r0.w;
            acc.x += r1.x; acc.y += r1.y; acc.z += r1.z; acc.w += r1.w;
            acc.x += r2.x; acc.y += r2.y; acc.z += r2.z; acc.w += r2.w;
            acc.x += r3.x; acc.y += r3.y; acc.z += r3.z; acc.w += r3.w;
        }
        for (; k < m; k++) {
            int e0 = __shfl_sync(0xffffffffu, idx, k);
            float4 r0 = __ldg(&messages4[(long long)e0 * Dq + col]);
            acc.x += r0.x; acc.y += r0.y; acc.z += r0.z; acc.w += r0.w;
        }
    }

    float inv = 1.0f / fmaxf((float)c, 1.0f);
    acc.x *= inv; acc.y *= inv; acc.z *= inv; acc.w *= inv;
    sums4[(long long)node * Dq + col] = acc;

    if (half == 0) {
        #pragma unroll
        for (int d = 16; d > 0; d >>= 1)
            emax = max(emax, __shfl_xor_sync(0xffffffffu, emax, d));
        if (lane == 0) {
            counts[node]  = (float)c;
            last_ts[node] = (c > 0) ? __ldg(&ts[emax]) : 0.0f;
        }
    }
}

extern "C" void kernel_launch(void* const* d_in, const int* in_sizes, int n_in,
                              void* d_out, int out_size) {
    const int*   node_ids   = (const int*)  d_in[0];
    const float* messages   = (const float*)d_in[1];
    const float* timestamps = (const float*)d_in[2];

    const int B   = in_sizes[0];
    const int D   = in_sizes[1] / B;            // 256
    const int N   = out_size / (D + 2);         // 100000
    const int Dq  = D / 4;                      // 64
    const int B4  = B / 4;
    const int NBS = (N + SCAN_CHUNK - 1) / SCAN_CHUNK;

    float* out     = (float*)d_out;
    float* sums    = out;                      // [N, D]
    float* last_ts = out + (long long)N * D;   // [N]
    float* counts  = last_ts + N;              // [N]

    void* zr_ptr = nullptr;
    cudaGetSymbolAddress(&zr_ptr, g_zero_region);

    // 1. zero barrier counter + histogram (single graph memset node)
    cudaMemsetAsync(zr_ptr, 0, (size_t)(64 + N) * sizeof(unsigned), 0);

    // 2. fused hist -> scan -> bin (single persistent kernel)
    prep_kernel<<<PREP_BLOCKS, PREP_THREADS>>>((const int4*)node_ids, B4,
                                               node_ids, B, N, NBS);

    // 3. gather + mean + count + last-ts (two warps per node)
    {
        int thr = 256;
        int warps_total = 2 * N;
        int warps_per_blk = thr / 32;
        int blocks = (warps_total + warps_per_blk - 1) / warps_per_blk;
        sum_kernel<<<blocks, thr>>>((const float4*)messages, timestamps,
                                    (float4*)sums, last_ts, counts, N, Dq);
    }
}